// round 13
// baseline (speedup 1.0000x reference)
#include <cuda_runtime.h>

// D = 16777216 floats per vector; n4 = D/4 float4 elements.
// Output: out[0..D) = x, out[D..D+6) = {ly0·x, ly1·x, ly1·ly0, ly2·x, ly2·ly0, ly2·ly1}
//
// CONVERGED CONFIGURATION (12 rounds of measurement):
//  - Traffic floor 320MB; loop plateau 48.1-48.6us = ~6.6TB/s for 4R:1W mix.
//  - Grid 4096x256, regs 32, simple grid-stride float4 loop. Measured worse:
//    unroll (R5: regs 54 -> occ 47%), persistent 1216 blocks (R6), 8192 blocks
//    (R10), .cs loads (R8). Kept: .cs store (R9, neutral-to-positive).
//  - Epilogue: fire-and-forget atomicAdd (REDG) into out_tail; NO __threadfence
//    anywhere (gpu-scope fence = CCTL.IVALL L1D flush, ~3us tax), no
//    ticket/last-block reduce (R4: serialized DRAM tail).
//  - R13: zero the 6-float tail via cudaMemsetAsync (native memset graph node,
//    no SM dispatch) instead of a kernel launch node.

#define NTHREADS 256
#define NBLOCKS  4096

#define DOT4(u, v) ((u).x*(v).x + (u).y*(v).y + (u).z*(v).z + (u).w*(v).w)

__global__ void __launch_bounds__(NTHREADS)
dlrm_fused_kernel(const float4* __restrict__ xv,
                  const float4* __restrict__ l0v,
                  const float4* __restrict__ l1v,
                  const float4* __restrict__ l2v,
                  float4* __restrict__ outx,
                  float* __restrict__ out_tail,
                  int n4) {
    float s0 = 0.f, s1 = 0.f, s2 = 0.f, s3 = 0.f, s4 = 0.f, s5 = 0.f;

    const int stride = gridDim.x * blockDim.x;
    for (int i = blockIdx.x * blockDim.x + threadIdx.x; i < n4; i += stride) {
        const float4 a = xv[i];
        const float4 b = l0v[i];
        const float4 c = l1v[i];
        const float4 d = l2v[i];
        __stcs(&outx[i], a);  // streaming store: output never re-read

        s0 += DOT4(b, a);  // ly0 · x
        s1 += DOT4(c, a);  // ly1 · x
        s2 += DOT4(c, b);  // ly1 · ly0
        s3 += DOT4(d, a);  // ly2 · x
        s4 += DOT4(d, b);  // ly2 · ly0
        s5 += DOT4(d, c);  // ly2 · ly1
    }

    // Warp-level reduction
    #pragma unroll
    for (int off = 16; off > 0; off >>= 1) {
        s0 += __shfl_down_sync(0xFFFFFFFFu, s0, off);
        s1 += __shfl_down_sync(0xFFFFFFFFu, s1, off);
        s2 += __shfl_down_sync(0xFFFFFFFFu, s2, off);
        s3 += __shfl_down_sync(0xFFFFFFFFu, s3, off);
        s4 += __shfl_down_sync(0xFFFFFFFFu, s4, off);
        s5 += __shfl_down_sync(0xFFFFFFFFu, s5, off);
    }

    __shared__ float smem[6][NTHREADS / 32];
    const int warp = threadIdx.x >> 5;
    const int lane = threadIdx.x & 31;
    if (lane == 0) {
        smem[0][warp] = s0; smem[1][warp] = s1; smem[2][warp] = s2;
        smem[3][warp] = s3; smem[4][warp] = s4; smem[5][warp] = s5;
    }
    __syncthreads();

    // Threads 0..5: one fire-and-forget atomicAdd each (REDG, no return wait).
    if (threadIdx.x < 6) {
        float v = 0.f;
        #pragma unroll
        for (int w = 0; w < NTHREADS / 32; w++) v += smem[threadIdx.x][w];
        atomicAdd(out_tail + threadIdx.x, v);
    }
}

extern "C" void kernel_launch(void* const* d_in, const int* in_sizes, int n_in,
                              void* d_out, int out_size) {
    const float* x  = (const float*)d_in[0];
    const float* l0 = (const float*)d_in[1];
    const float* l1 = (const float*)d_in[2];
    const float* l2 = (const float*)d_in[3];
    float* out = (float*)d_out;

    const int D  = in_sizes[0];   // 16777216
    const int n4 = D / 4;         // 4194304

    // Zero the 6-float tail via a native memset node (graph-capturable,
    // no SM dispatch). IEEE-754 zero is all-zero bytes.
    cudaMemsetAsync(out + D, 0, 6 * sizeof(float));

    int blocks = NBLOCKS;
    const int maxBlocks = (n4 + NTHREADS - 1) / NTHREADS;
    if (blocks > maxBlocks) blocks = maxBlocks;

    dlrm_fused_kernel<<<blocks, NTHREADS>>>(
        (const float4*)x, (const float4*)l0, (const float4*)l1, (const float4*)l2,
        (float4*)out, out + D, n4);
}

// round 14
// speedup vs baseline: 1.0168x; 1.0168x over previous
#include <cuda_runtime.h>

// D = 16777216 floats per vector; n4 = D/4 float4 elements.
// Output: out[0..D) = x, out[D..D+6) = {ly0·x, ly1·x, ly1·ly0, ly2·x, ly2·ly0, ly2·ly1}
//
// FINAL CONFIGURATION — exact replication of the best-observed run (R1, 53.31us).
// 13 rounds of single-variable measurement established:
//  - Traffic floor 320MB (4 reads + 1 write, each byte once). Loop plateau
//    48.1-49.3us = 6.4-6.6TB/s: the HBM ceiling for a 4R:1W mix (LTS at ~55%
//    of its cap -> DRAM devices bind, not the L2 fabric).
//  - Grid 4096x256, regs 32. Worse: in-thread unroll (regs 54 -> occ 47%),
//    1216-block persistent grid, 8192 blocks. Cache hints: .cs loads negative,
//    .cs store within noise but 0/4 runs below 53.5 vs 1/1 for plain store.
//  - NO __threadfence anywhere (gpu-scope fence = CCTL.IVALL L1D flush, ~3us).
//  - NO last-block/ticket reduce (serialized DRAM-latency tail, ~8us/~1us).
//  - Epilogue: 6 fire-and-forget atomicAdds (REDG, no return wait) into
//    out_tail, pre-zeroed by a 1-warp kernel (node cost within harness noise).

#define NTHREADS 256
#define NBLOCKS  4096

#define DOT4(u, v) ((u).x*(v).x + (u).y*(v).y + (u).z*(v).z + (u).w*(v).w)

__global__ void zero_tail_kernel(float* __restrict__ out_tail) {
    if (threadIdx.x < 6) out_tail[threadIdx.x] = 0.0f;
}

__global__ void __launch_bounds__(NTHREADS)
dlrm_fused_kernel(const float4* __restrict__ xv,
                  const float4* __restrict__ l0v,
                  const float4* __restrict__ l1v,
                  const float4* __restrict__ l2v,
                  float4* __restrict__ outx,
                  float* __restrict__ out_tail,
                  int n4) {
    float s0 = 0.f, s1 = 0.f, s2 = 0.f, s3 = 0.f, s4 = 0.f, s5 = 0.f;

    const int stride = gridDim.x * blockDim.x;
    for (int i = blockIdx.x * blockDim.x + threadIdx.x; i < n4; i += stride) {
        const float4 a = xv[i];
        const float4 b = l0v[i];
        const float4 c = l1v[i];
        const float4 d = l2v[i];
        outx[i] = a;  // fused copy of x into out (plain store)

        s0 += DOT4(b, a);  // ly0 · x
        s1 += DOT4(c, a);  // ly1 · x
        s2 += DOT4(c, b);  // ly1 · ly0
        s3 += DOT4(d, a);  // ly2 · x
        s4 += DOT4(d, b);  // ly2 · ly0
        s5 += DOT4(d, c);  // ly2 · ly1
    }

    // Warp-level reduction
    #pragma unroll
    for (int off = 16; off > 0; off >>= 1) {
        s0 += __shfl_down_sync(0xFFFFFFFFu, s0, off);
        s1 += __shfl_down_sync(0xFFFFFFFFu, s1, off);
        s2 += __shfl_down_sync(0xFFFFFFFFu, s2, off);
        s3 += __shfl_down_sync(0xFFFFFFFFu, s3, off);
        s4 += __shfl_down_sync(0xFFFFFFFFu, s4, off);
        s5 += __shfl_down_sync(0xFFFFFFFFu, s5, off);
    }

    __shared__ float smem[6][NTHREADS / 32];
    const int warp = threadIdx.x >> 5;
    const int lane = threadIdx.x & 31;
    if (lane == 0) {
        smem[0][warp] = s0; smem[1][warp] = s1; smem[2][warp] = s2;
        smem[3][warp] = s3; smem[4][warp] = s4; smem[5][warp] = s5;
    }
    __syncthreads();

    // Threads 0..5: one fire-and-forget atomicAdd each (REDG, no return wait).
    if (threadIdx.x < 6) {
        float v = 0.f;
        #pragma unroll
        for (int w = 0; w < NTHREADS / 32; w++) v += smem[threadIdx.x][w];
        atomicAdd(out_tail + threadIdx.x, v);
    }
}

extern "C" void kernel_launch(void* const* d_in, const int* in_sizes, int n_in,
                              void* d_out, int out_size) {
    const float* x  = (const float*)d_in[0];
    const float* l0 = (const float*)d_in[1];
    const float* l1 = (const float*)d_in[2];
    const float* l2 = (const float*)d_in[3];
    float* out = (float*)d_out;

    const int D  = in_sizes[0];   // 16777216
    const int n4 = D / 4;         // 4194304

    zero_tail_kernel<<<1, 32>>>(out + D);

    int blocks = NBLOCKS;
    const int maxBlocks = (n4 + NTHREADS - 1) / NTHREADS;
    if (blocks > maxBlocks) blocks = maxBlocks;

    dlrm_fused_kernel<<<blocks, NTHREADS>>>(
        (const float4*)x, (const float4*)l0, (const float4*)l1, (const float4*)l2,
        (float4*)out, out + D, n4);
}